// round 1
// baseline (speedup 1.0000x reference)
#include <cuda_runtime.h>

// DotProcessorBlock: feat = x*w + b (per row, N=256)
// out[b, k] = feat[k>>8] * feat[k&255] for k in [0, 32896)
// B=4096 rows. Output ~539 MB -> pure HBM-write-bound kernel.

#define N_FEAT 256
#define NUM_OUT 32896          // N*(N+1)/2
#define OUT_VEC4 (NUM_OUT / 4) // 8224 float4 per row

__global__ __launch_bounds__(256, 8)
void dot_outer_kernel(const float* __restrict__ x,
                      const float* __restrict__ w,
                      const float* __restrict__ bias,
                      float* __restrict__ out)
{
    __shared__ float feat_s[N_FEAT];

    const int row = blockIdx.x;
    const int tid = threadIdx.x;

    // One FFMA per thread: feat = x*w + b
    feat_s[tid] = fmaf(x[row * N_FEAT + tid], w[tid], bias[tid]);
    __syncthreads();

    float4* __restrict__ out4 = reinterpret_cast<float4*>(out) + (size_t)row * OUT_VEC4;
    const float4* feat4 = reinterpret_cast<const float4*>(feat_s);

    // 8224 float4 per row: 32 full strided iterations of 256 threads,
    // then a 32-float4 tail handled by the first 32 threads.
    #pragma unroll 4
    for (int t = tid; t < OUT_VEC4; t += 256) {
        const int k = t << 2;           // scalar output index
        const float fi = feat_s[k >> 8];
        float4 fj = feat4[(k & 255) >> 2];
        fj.x *= fi; fj.y *= fi; fj.z *= fi; fj.w *= fi;
        out4[t] = fj;
    }
}

extern "C" void kernel_launch(void* const* d_in, const int* in_sizes, int n_in,
                              void* d_out, int out_size)
{
    const float* x    = (const float*)d_in[0];
    const float* w    = (const float*)d_in[1];
    const float* bias = (const float*)d_in[2];
    float* out        = (float*)d_out;

    const int B = in_sizes[0] / N_FEAT;   // 4096
    dot_outer_kernel<<<B, 256>>>(x, w, bias, out);
}

// round 2
// speedup vs baseline: 1.0337x; 1.0337x over previous
#include <cuda_runtime.h>

// DotProcessorBlock: feat = x*w + b (per row, N=256)
// out[b, k] = feat[k>>8] * feat[k&255] for k in [0, 32896)
// B=4096 rows. Output ~539 MB -> pure HBM-write-bound kernel.
// R2: streaming stores (__stcs) so dead output lines don't compete for L2.

#define N_FEAT 256
#define NUM_OUT 32896          // N*(N+1)/2
#define OUT_VEC4 (NUM_OUT / 4) // 8224 float4 per row

__global__ __launch_bounds__(256, 8)
void dot_outer_kernel(const float* __restrict__ x,
                      const float* __restrict__ w,
                      const float* __restrict__ bias,
                      float* __restrict__ out)
{
    __shared__ float feat_s[N_FEAT];

    const int row = blockIdx.x;
    const int tid = threadIdx.x;

    // One FFMA per thread: feat = x*w + b
    feat_s[tid] = fmaf(x[row * N_FEAT + tid], w[tid], bias[tid]);
    __syncthreads();

    float4* __restrict__ out4 = reinterpret_cast<float4*>(out) + (size_t)row * OUT_VEC4;
    const float4* feat4 = reinterpret_cast<const float4*>(feat_s);

    // 8224 float4 per row = 32 full strided iterations of 256 threads + 32-wide tail.
    // Streaming stores: output is never re-read; evict-first in L2.
    #pragma unroll 4
    for (int t = tid; t < OUT_VEC4; t += 256) {
        const int k = t << 2;           // scalar output index
        const float fi = feat_s[k >> 8];
        float4 fj = feat4[(k & 255) >> 2];
        fj.x *= fi; fj.y *= fi; fj.z *= fi; fj.w *= fi;
        __stcs(&out4[t], fj);
    }
}

extern "C" void kernel_launch(void* const* d_in, const int* in_sizes, int n_in,
                              void* d_out, int out_size)
{
    const float* x    = (const float*)d_in[0];
    const float* w    = (const float*)d_in[1];
    const float* bias = (const float*)d_in[2];
    float* out        = (float*)d_out;

    const int B = in_sizes[0] / N_FEAT;   // 4096
    dot_outer_kernel<<<B, 256>>>(x, w, bias, out);
}

// round 3
// speedup vs baseline: 1.1013x; 1.0654x over previous
#include <cuda_runtime.h>

// DotProcessorBlock: feat = x*w + b (per row, N=256)
// out[b, k] = feat[k>>8] * feat[k&255] for k in [0, 32896)
// B=4096 rows, ~539 MB of pure stores -> HBM-write-bound.
// R3: split each row into 8 chunks (grid=32768) to shrink the end-of-kernel
//     drain tail from ~1 CTA-lifetime (~13us of lost BW) to ~1.6us.

#define N_FEAT 256
#define NUM_OUT 32896            // N*(N+1)/2
#define OUT_VEC4 (NUM_OUT / 4)   // 8224 float4 per row
#define CHUNKS 8                 // chunks per row
#define CHUNK_V4 (OUT_VEC4 / CHUNKS) // 1028 float4 per chunk

__global__ __launch_bounds__(256, 8)
void dot_outer_kernel(const float* __restrict__ x,
                      const float* __restrict__ w,
                      const float* __restrict__ bias,
                      float* __restrict__ out)
{
    __shared__ float feat_s[N_FEAT];

    const int row   = blockIdx.x >> 3;       // / CHUNKS
    const int chunk = blockIdx.x & (CHUNKS - 1);
    const int tid   = threadIdx.x;

    // feat = x*w + b (x row / w / b are L2-resident across the 8 replicas)
    feat_s[tid] = fmaf(x[row * N_FEAT + tid], w[tid], bias[tid]);
    __syncthreads();

    float4* __restrict__ out4 = reinterpret_cast<float4*>(out) + (size_t)row * OUT_VEC4;
    const float4* feat4 = reinterpret_cast<const float4*>(feat_s);

    const int base = chunk * CHUNK_V4;
    const int end  = base + CHUNK_V4;

    // Per-thread fj index (t & 63) is invariant under t += 256: hoist it.
    const int t0 = base + tid;
    float4 fj = feat4[t0 & 63];

    // 1028 float4 per chunk: 4 full iterations + 4-thread remainder.
    #pragma unroll 4
    for (int t = t0; t < end; t += 256) {
        const float fi = feat_s[t >> 6];     // (4t)>>8 == t>>6, near-broadcast
        float4 v;
        v.x = fj.x * fi; v.y = fj.y * fi; v.z = fj.z * fi; v.w = fj.w * fi;
        __stcs(&out4[t], v);
    }
}

extern "C" void kernel_launch(void* const* d_in, const int* in_sizes, int n_in,
                              void* d_out, int out_size)
{
    const float* x    = (const float*)d_in[0];
    const float* w    = (const float*)d_in[1];
    const float* bias = (const float*)d_in[2];
    float* out        = (float*)d_out;

    const int B = in_sizes[0] / N_FEAT;   // 4096
    dot_outer_kernel<<<B * CHUNKS, 256>>>(x, w, bias, out);
}